// round 1
// baseline (speedup 1.0000x reference)
#include <cuda_runtime.h>
#include <math.h>

#define BATCH 2
#define S_LEN 2048
#define D_MODEL 1024
#define NHEAD 16
#define DHEAD 64
#define NEGBIG -1e30f

// Scratch (allocation-free rule: __device__ globals)
__device__ float g_q[BATCH*NHEAD*S_LEN*DHEAD];
__device__ float g_k[BATCH*NHEAD*S_LEN*DHEAD];
__device__ float g_v[BATCH*NHEAD*S_LEN*DHEAD];
__device__ float g_att[BATCH*S_LEN*D_MODEL];

// ---------------------------------------------------------------------------
// Kernel A: QKV projection. x (4096x1024) @ W_qkv (1024x3072).
// 128x128 tile, BK=8, 256 threads, 8x8 per thread. Epilogue scatters into
// q/k/v in (b,h,s,dh) layout.
// ---------------------------------------------------------------------------
__global__ void qkv_gemm_kernel(const float* __restrict__ A,
                                const float* __restrict__ B)
{
    const int K = 1024, N = 3072;
    __shared__ float As[8][128];
    __shared__ float Bs[8][128];
    const int tid = threadIdx.x;
    const int m0 = blockIdx.y * 128;
    const int n0 = blockIdx.x * 128;
    const int ty = tid >> 4, tx = tid & 15;
    const int arow = tid >> 1;
    const int akq  = (tid & 1) * 4;
    const int brow = tid >> 5;
    const int bcol = (tid & 31) * 4;

    float acc[8][8];
    #pragma unroll
    for (int i = 0; i < 8; i++)
        #pragma unroll
        for (int j = 0; j < 8; j++) acc[i][j] = 0.f;

    for (int k0 = 0; k0 < K; k0 += 8) {
        float4 a4 = *reinterpret_cast<const float4*>(A + (long)(m0 + arow)*K + k0 + akq);
        As[akq+0][arow] = a4.x; As[akq+1][arow] = a4.y;
        As[akq+2][arow] = a4.z; As[akq+3][arow] = a4.w;
        float4 b4 = *reinterpret_cast<const float4*>(B + (long)(k0 + brow)*N + n0 + bcol);
        *reinterpret_cast<float4*>(&Bs[brow][bcol]) = b4;
        __syncthreads();
        #pragma unroll
        for (int kk = 0; kk < 8; kk++) {
            float ra[8], rb[8];
            #pragma unroll
            for (int i = 0; i < 8; i++) ra[i] = As[kk][ty*8+i];
            #pragma unroll
            for (int j = 0; j < 8; j++) rb[j] = Bs[kk][tx*8+j];
            #pragma unroll
            for (int i = 0; i < 8; i++)
                #pragma unroll
                for (int j = 0; j < 8; j++)
                    acc[i][j] = fmaf(ra[i], rb[j], acc[i][j]);
        }
        __syncthreads();
    }

    #pragma unroll
    for (int i = 0; i < 8; i++) {
        int r = m0 + ty*8 + i;
        int b = r >> 11, s = r & 2047;
        #pragma unroll
        for (int j = 0; j < 8; j++) {
            int c = n0 + tx*8 + j;
            int which = c >> 10;
            int h  = (c >> 6) & 15;
            int dh = c & 63;
            long idx = (((long)(b*NHEAD + h))*S_LEN + s)*DHEAD + dh;
            float* dst = (which == 0) ? g_q : (which == 1) ? g_k : g_v;
            dst[idx] = acc[i][j];
        }
    }
}

// ---------------------------------------------------------------------------
// Kernel B: banded attention. Per (b,h), 64-query tile; keys restricted to
// [qstart-128, qstart+63] (192 keys) by causal+window masks.
// Dynamic smem: Q 16KB | K 48KB | V 48KB | S 48KB = 160KB.
// ---------------------------------------------------------------------------
#define ATTN_SMEM_FLOATS (4096 + 12288 + 12288 + 12288)

__global__ void attn_kernel(const float* __restrict__ bias)
{
    extern __shared__ float sm[];
    float* Qs = sm;                       // [64][64]
    float* Ks = sm + 4096;                // [192][64]
    float* Vs = sm + 4096 + 12288;        // [192][64]
    float* Ss = sm + 4096 + 2*12288;      // [64][192]

    const int tid = threadIdx.x;
    const int qt = blockIdx.x;   // 0..31
    const int bh = blockIdx.y;   // 0..31  (b*16+h)
    const int qstart = qt * 64;
    const int jbase = qstart - 128;

    const float* qg = g_q + (long)bh * S_LEN * DHEAD;
    const float* kg = g_k + (long)bh * S_LEN * DHEAD;
    const float* vg = g_v + (long)bh * S_LEN * DHEAD;

    for (int idx = tid; idx < 64*64; idx += 256)
        Qs[idx] = qg[(long)(qstart + (idx >> 6))*DHEAD + (idx & 63)];
    for (int idx = tid; idx < 192*64; idx += 256) {
        int j = jbase + (idx >> 6);
        float kv = 0.f, vv = 0.f;
        if (j >= 0) {
            kv = kg[(long)j*DHEAD + (idx & 63)];
            vv = vg[(long)j*DHEAD + (idx & 63)];
        }
        Ks[idx] = kv; Vs[idx] = vv;
    }
    __syncthreads();

    const int ty = tid >> 4, tx = tid & 15;

    // ---- Phase 1: S = Q K^T (64 x 192), + scale + bias + masks ----
    {
        float acc[4][12];
        #pragma unroll
        for (int i = 0; i < 4; i++)
            #pragma unroll
            for (int j = 0; j < 12; j++) acc[i][j] = 0.f;

        for (int k = 0; k < 64; k++) {
            float rq[4], rk[12];
            #pragma unroll
            for (int i = 0; i < 4; i++) rq[i] = Qs[(ty*4+i)*64 + k];
            #pragma unroll
            for (int j = 0; j < 12; j++) rk[j] = Ks[(tx*12+j)*64 + k];
            #pragma unroll
            for (int i = 0; i < 4; i++)
                #pragma unroll
                for (int j = 0; j < 12; j++)
                    acc[i][j] = fmaf(rq[i], rk[j], acc[i][j]);
        }

        const float scale = 0.125f;  // 1/sqrt(64)
        const float* bb = bias + (long)bh * S_LEN * S_LEN;
        #pragma unroll
        for (int i = 0; i < 4; i++) {
            int gi = qstart + ty*4 + i;
            #pragma unroll
            for (int j = 0; j < 12; j++) {
                int c = tx*12 + j;
                int gj = jbase + c;
                float val = NEGBIG;
                if (gj >= 0 && gj <= gi && (gi - gj) <= 128)
                    val = acc[i][j]*scale + bb[(long)gi*S_LEN + gj];
                Ss[(ty*4+i)*192 + c] = val;
            }
        }
    }
    __syncthreads();

    // ---- Phase 2: row softmax (one warp per 8 rows) ----
    {
        const int w = tid >> 5, lane = tid & 31;
        for (int rr = 0; rr < 8; rr++) {
            int r = w*8 + rr;
            float vals[6];
            float m = NEGBIG;
            #pragma unroll
            for (int t = 0; t < 6; t++) {
                vals[t] = Ss[r*192 + t*32 + lane];
                m = fmaxf(m, vals[t]);
            }
            #pragma unroll
            for (int o = 16; o > 0; o >>= 1)
                m = fmaxf(m, __shfl_xor_sync(0xffffffffu, m, o));
            float ssum = 0.f;
            #pragma unroll
            for (int t = 0; t < 6; t++) {
                vals[t] = __expf(vals[t] - m);
                ssum += vals[t];
            }
            #pragma unroll
            for (int o = 16; o > 0; o >>= 1)
                ssum += __shfl_xor_sync(0xffffffffu, ssum, o);
            float inv = 1.f / ssum;
            #pragma unroll
            for (int t = 0; t < 6; t++)
                Ss[r*192 + t*32 + lane] = vals[t] * inv;
        }
    }
    __syncthreads();

    // ---- Phase 3: O = P V (64 x 64) ----
    {
        float acc[4][4];
        #pragma unroll
        for (int i = 0; i < 4; i++)
            #pragma unroll
            for (int j = 0; j < 4; j++) acc[i][j] = 0.f;

        for (int k = 0; k < 192; k++) {
            float rp[4], rv[4];
            #pragma unroll
            for (int i = 0; i < 4; i++) rp[i] = Ss[(ty*4+i)*192 + k];
            #pragma unroll
            for (int j = 0; j < 4; j++) rv[j] = Vs[k*64 + tx*4 + j];
            #pragma unroll
            for (int i = 0; i < 4; i++)
                #pragma unroll
                for (int j = 0; j < 4; j++)
                    acc[i][j] = fmaf(rp[i], rv[j], acc[i][j]);
        }

        const int b = bh >> 4, h = bh & 15;
        #pragma unroll
        for (int i = 0; i < 4; i++) {
            int gi = qstart + ty*4 + i;
            #pragma unroll
            for (int j = 0; j < 4; j++) {
                g_att[((long)(b*S_LEN + gi))*D_MODEL + h*DHEAD + tx*4 + j] = acc[i][j];
            }
        }
    }
}

// ---------------------------------------------------------------------------
// Kernel C: output projection. g_att (4096x1024) @ W_out (1024x1024) -> out.
// ---------------------------------------------------------------------------
__global__ void out_gemm_kernel(const float* __restrict__ B,
                                float* __restrict__ Out)
{
    const int K = 1024, N = 1024;
    const float* A = g_att;
    __shared__ float As[8][128];
    __shared__ float Bs[8][128];
    const int tid = threadIdx.x;
    const int m0 = blockIdx.y * 128;
    const int n0 = blockIdx.x * 128;
    const int ty = tid >> 4, tx = tid & 15;
    const int arow = tid >> 1;
    const int akq  = (tid & 1) * 4;
    const int brow = tid >> 5;
    const int bcol = (tid & 31) * 4;

    float acc[8][8];
    #pragma unroll
    for (int i = 0; i < 8; i++)
        #pragma unroll
        for (int j = 0; j < 8; j++) acc[i][j] = 0.f;

    for (int k0 = 0; k0 < K; k0 += 8) {
        float4 a4 = *reinterpret_cast<const float4*>(A + (long)(m0 + arow)*K + k0 + akq);
        As[akq+0][arow] = a4.x; As[akq+1][arow] = a4.y;
        As[akq+2][arow] = a4.z; As[akq+3][arow] = a4.w;
        float4 b4 = *reinterpret_cast<const float4*>(B + (long)(k0 + brow)*N + n0 + bcol);
        *reinterpret_cast<float4*>(&Bs[brow][bcol]) = b4;
        __syncthreads();
        #pragma unroll
        for (int kk = 0; kk < 8; kk++) {
            float ra[8], rb[8];
            #pragma unroll
            for (int i = 0; i < 8; i++) ra[i] = As[kk][ty*8+i];
            #pragma unroll
            for (int j = 0; j < 8; j++) rb[j] = Bs[kk][tx*8+j];
            #pragma unroll
            for (int i = 0; i < 8; i++)
                #pragma unroll
                for (int j = 0; j < 8; j++)
                    acc[i][j] = fmaf(ra[i], rb[j], acc[i][j]);
        }
        __syncthreads();
    }

    #pragma unroll
    for (int i = 0; i < 8; i++) {
        int r = m0 + ty*8 + i;
        #pragma unroll
        for (int j = 0; j < 8; j++) {
            int c = n0 + tx*8 + j;
            Out[(long)r*N + c] = acc[i][j];
        }
    }
}

// ---------------------------------------------------------------------------
extern "C" void kernel_launch(void* const* d_in, const int* in_sizes, int n_in,
                              void* d_out, int out_size)
{
    const float* x    = (const float*)d_in[0];
    const float* bias = (const float*)d_in[1];
    // d_in[2] = causal mask (recomputed analytically in-kernel)
    const float* Wqkv = (const float*)d_in[3];
    const float* Wout = (const float*)d_in[4];
    float* out = (float*)d_out;

    cudaFuncSetAttribute(attn_kernel,
                         cudaFuncAttributeMaxDynamicSharedMemorySize,
                         ATTN_SMEM_FLOATS * (int)sizeof(float));

    // A: QKV projection  (M=4096, N=3072)
    qkv_gemm_kernel<<<dim3(24, 32), 256>>>(x, Wqkv);

    // B: banded attention (32 q-tiles x 32 (b,h))
    attn_kernel<<<dim3(32, 32), 256, ATTN_SMEM_FLOATS * (int)sizeof(float)>>>(bias);

    // C: output projection (M=4096, N=1024)
    out_gemm_kernel<<<dim3(8, 32), 256>>>(Wout, out);
}

// round 2
// speedup vs baseline: 1.4544x; 1.4544x over previous
#include <cuda_runtime.h>
#include <math.h>
#include <stdint.h>

#define BATCH 2
#define S_LEN 2048
#define D_MODEL 1024
#define NHEAD 16
#define DHEAD 64
#define NEGBIG -1e30f

// Scratch (allocation-free rule: __device__ globals)
__device__ float g_q[BATCH*NHEAD*S_LEN*DHEAD];
__device__ float g_k[BATCH*NHEAD*S_LEN*DHEAD];
__device__ float g_v[BATCH*NHEAD*S_LEN*DHEAD];
__device__ float g_att[BATCH*S_LEN*D_MODEL];

// ---------------------------------------------------------------------------
// 3xTF32 GEMM: C = A(MxK) @ B(KxN), K=1024, fp32-accurate via hi/lo split.
// BM=BN=128, BK=16, 256 threads (8 warps, 4x2 grid of 32x64 warp tiles).
// cp.async double-buffered smem. Epilogue: QKV scatter or plain store.
// ---------------------------------------------------------------------------
#define BM 128
#define BN 128
#define BKT 16
#define APITCH 20   // 128 rows x 20 floats (pad for conflict-free frag loads)
#define BPITCH 132  // 16 rows x 132 floats

__device__ __forceinline__ uint32_t f2tf32(float x) {
    uint32_t r;
    asm("cvt.rna.tf32.f32 %0, %1;" : "=r"(r) : "f"(x));
    return r;
}

__device__ __forceinline__ void split_tf32(float x, uint32_t& hi, uint32_t& lo) {
    hi = f2tf32(x);
    float res = x - __uint_as_float(hi);
    lo = f2tf32(res);
}

__device__ __forceinline__ void cpasync16(float* smem, const float* g) {
    uint32_t s = (uint32_t)__cvta_generic_to_shared(smem);
    asm volatile("cp.async.cg.shared.global [%0], [%1], 16;\n" :: "r"(s), "l"(g));
}

__device__ __forceinline__ void mma_tf32(float* c, const uint32_t* a, const uint32_t* b) {
    asm volatile(
        "mma.sync.aligned.m16n8k8.row.col.f32.tf32.tf32.f32 "
        "{%0,%1,%2,%3}, {%4,%5,%6,%7}, {%8,%9}, {%0,%1,%2,%3};"
        : "+f"(c[0]), "+f"(c[1]), "+f"(c[2]), "+f"(c[3])
        : "r"(a[0]), "r"(a[1]), "r"(a[2]), "r"(a[3]), "r"(b[0]), "r"(b[1]));
}

template<int N, bool IS_QKV>
__global__ void tf32_gemm_kernel(const float* __restrict__ Ain,
                                 const float* __restrict__ Bw,
                                 float* __restrict__ Out)
{
    __shared__ float As[2][BM*APITCH];
    __shared__ float Bs[2][BKT*BPITCH];
    const int K = 1024;
    const float* A = IS_QKV ? Ain : (const float*)g_att;

    const int tid  = threadIdx.x;
    const int lane = tid & 31;
    const int wid  = tid >> 5;
    const int wm   = wid & 3;      // 0..3  -> 32-row slab
    const int wn   = wid >> 2;     // 0..1  -> 64-col slab
    const int m0 = blockIdx.y * BM;
    const int n0 = blockIdx.x * BN;

    float acc[2][8][4];
    #pragma unroll
    for (int mt = 0; mt < 2; mt++)
        #pragma unroll
        for (int nt = 0; nt < 8; nt++)
            #pragma unroll
            for (int i = 0; i < 4; i++) acc[mt][nt][i] = 0.f;

    // ---- tile loader: A 128x16 (row-major, pitch 20), B 16x128 (pitch 132)
    auto load_tiles = [&](int k0, int buf) {
        #pragma unroll
        for (int u = 0; u < 2; u++) {
            int c = tid + u * 256;                 // 512 16B chunks
            int row = c >> 2, kc = (c & 3) * 4;
            cpasync16(&As[buf][row*APITCH + kc], A + (long)(m0+row)*K + k0 + kc);
        }
        #pragma unroll
        for (int u = 0; u < 2; u++) {
            int c = tid + u * 256;
            int kr = c >> 5, nc = (c & 31) * 4;
            cpasync16(&Bs[buf][kr*BPITCH + nc], Bw + (long)(k0+kr)*N + n0 + nc);
        }
        asm volatile("cp.async.commit_group;\n");
    };

    load_tiles(0, 0);

    const int NIT = K / BKT;
    for (int it = 0; it < NIT; ++it) {
        asm volatile("cp.async.wait_group 0;\n");
        __syncthreads();
        if (it + 1 < NIT) load_tiles((it+1)*BKT, (it+1) & 1);

        const float* As_ = As[it & 1];
        const float* Bs_ = Bs[it & 1];

        #pragma unroll
        for (int ks = 0; ks < 2; ks++) {
            const int kb = ks * 8;
            uint32_t ah[2][4], al[2][4];
            #pragma unroll
            for (int mt = 0; mt < 2; mt++) {
                int r = wm*32 + mt*16 + (lane >> 2);
                int c = kb + (lane & 3);
                split_tf32(As_[r*APITCH + c],        ah[mt][0], al[mt][0]);
                split_tf32(As_[(r+8)*APITCH + c],    ah[mt][1], al[mt][1]);
                split_tf32(As_[r*APITCH + c + 4],    ah[mt][2], al[mt][2]);
                split_tf32(As_[(r+8)*APITCH + c + 4],ah[mt][3], al[mt][3]);
            }
            uint32_t bh[8][2], bl[8][2];
            #pragma unroll
            for (int nt = 0; nt < 8; nt++) {
                int bc = wn*64 + nt*8 + (lane >> 2);
                int br = kb + (lane & 3);
                split_tf32(Bs_[br*BPITCH + bc],     bh[nt][0], bl[nt][0]);
                split_tf32(Bs_[(br+4)*BPITCH + bc], bh[nt][1], bl[nt][1]);
            }
            #pragma unroll
            for (int mt = 0; mt < 2; mt++)
                #pragma unroll
                for (int nt = 0; nt < 8; nt++) {
                    mma_tf32(acc[mt][nt], ah[mt], bl[nt]);  // hi*lo
                    mma_tf32(acc[mt][nt], al[mt], bh[nt]);  // lo*hi
                    mma_tf32(acc[mt][nt], ah[mt], bh[nt]);  // hi*hi (last: biggest term)
                }
        }
        __syncthreads();
    }

    // ---- epilogue ----
    #pragma unroll
    for (int mt = 0; mt < 2; mt++) {
        #pragma unroll
        for (int i = 0; i < 2; i++) {
            int row = m0 + wm*32 + mt*16 + (lane >> 2) + i*8;
            #pragma unroll
            for (int nt = 0; nt < 8; nt++) {
                int col = n0 + wn*64 + nt*8 + (lane & 3)*2;
                float2 v = make_float2(acc[mt][nt][i*2+0], acc[mt][nt][i*2+1]);
                if (IS_QKV) {
                    int b = row >> 11, s = row & 2047;
                    int which = col >> 10;
                    int h = (col >> 6) & 15;
                    int dh = col & 63;
                    float* dst = (which == 0) ? g_q : (which == 1) ? g_k : g_v;
                    *reinterpret_cast<float2*>(
                        &dst[(((long)(b*NHEAD + h))*S_LEN + s)*DHEAD + dh]) = v;
                } else {
                    *reinterpret_cast<float2*>(&Out[(long)row*N + col]) = v;
                }
            }
        }
    }
}

// ---------------------------------------------------------------------------
// Kernel B: banded attention (unchanged from R1). Per (b,h), 64-query tile;
// keys restricted to [qstart-128, qstart+63] (192 keys).
// ---------------------------------------------------------------------------
#define ATTN_SMEM_FLOATS (4096 + 12288 + 12288 + 12288)

__global__ void attn_kernel(const float* __restrict__ bias)
{
    extern __shared__ float sm[];
    float* Qs = sm;                       // [64][64]
    float* Ks = sm + 4096;                // [192][64]
    float* Vs = sm + 4096 + 12288;        // [192][64]
    float* Ss = sm + 4096 + 2*12288;      // [64][192]

    const int tid = threadIdx.x;
    const int qt = blockIdx.x;
    const int bh = blockIdx.y;
    const int qstart = qt * 64;
    const int jbase = qstart - 128;

    const float* qg = g_q + (long)bh * S_LEN * DHEAD;
    const float* kg = g_k + (long)bh * S_LEN * DHEAD;
    const float* vg = g_v + (long)bh * S_LEN * DHEAD;

    for (int idx = tid; idx < 64*64; idx += 256)
        Qs[idx] = qg[(long)(qstart + (idx >> 6))*DHEAD + (idx & 63)];
    for (int idx = tid; idx < 192*64; idx += 256) {
        int j = jbase + (idx >> 6);
        float kv = 0.f, vv = 0.f;
        if (j >= 0) {
            kv = kg[(long)j*DHEAD + (idx & 63)];
            vv = vg[(long)j*DHEAD + (idx & 63)];
        }
        Ks[idx] = kv; Vs[idx] = vv;
    }
    __syncthreads();

    const int ty = tid >> 4, tx = tid & 15;

    // ---- Phase 1: S = Q K^T + scale + bias + masks ----
    {
        float acc[4][12];
        #pragma unroll
        for (int i = 0; i < 4; i++)
            #pragma unroll
            for (int j = 0; j < 12; j++) acc[i][j] = 0.f;

        for (int k = 0; k < 64; k++) {
            float rq[4], rk[12];
            #pragma unroll
            for (int i = 0; i < 4; i++) rq[i] = Qs[(ty*4+i)*64 + k];
            #pragma unroll
            for (int j = 0; j < 12; j++) rk[j] = Ks[(tx*12+j)*64 + k];
            #pragma unroll
            for (int i = 0; i < 4; i++)
                #pragma unroll
                for (int j = 0; j < 12; j++)
                    acc[i][j] = fmaf(rq[i], rk[j], acc[i][j]);
        }

        const float scale = 0.125f;
        const float* bb = bias + (long)bh * S_LEN * S_LEN;
        #pragma unroll
        for (int i = 0; i < 4; i++) {
            int gi = qstart + ty*4 + i;
            #pragma unroll
            for (int j = 0; j < 12; j++) {
                int c = tx*12 + j;
                int gj = jbase + c;
                float val = NEGBIG;
                if (gj >= 0 && gj <= gi && (gi - gj) <= 128)
                    val = acc[i][j]*scale + bb[(long)gi*S_LEN + gj];
                Ss[(ty*4+i)*192 + c] = val;
            }
        }
    }
    __syncthreads();

    // ---- Phase 2: row softmax ----
    {
        const int w = tid >> 5, lane = tid & 31;
        for (int rr = 0; rr < 8; rr++) {
            int r = w*8 + rr;
            float vals[6];
            float m = NEGBIG;
            #pragma unroll
            for (int t = 0; t < 6; t++) {
                vals[t] = Ss[r*192 + t*32 + lane];
                m = fmaxf(m, vals[t]);
            }
            #pragma unroll
            for (int o = 16; o > 0; o >>= 1)
                m = fmaxf(m, __shfl_xor_sync(0xffffffffu, m, o));
            float ssum = 0.f;
            #pragma unroll
            for (int t = 0; t < 6; t++) {
                vals[t] = __expf(vals[t] - m);
                ssum += vals[t];
            }
            #pragma unroll
            for (int o = 16; o > 0; o >>= 1)
                ssum += __shfl_xor_sync(0xffffffffu, ssum, o);
            float inv = 1.f / ssum;
            #pragma unroll
            for (int t = 0; t < 6; t++)
                Ss[r*192 + t*32 + lane] = vals[t] * inv;
        }
    }
    __syncthreads();

    // ---- Phase 3: O = P V ----
    {
        float acc[4][4];
        #pragma unroll
        for (int i = 0; i < 4; i++)
            #pragma unroll
            for (int j = 0; j < 4; j++) acc[i][j] = 0.f;

        for (int k = 0; k < 192; k++) {
            float rp[4], rv[4];
            #pragma unroll
            for (int i = 0; i < 4; i++) rp[i] = Ss[(ty*4+i)*192 + k];
            #pragma unroll
            for (int j = 0; j < 4; j++) rv[j] = Vs[k*64 + tx*4 + j];
            #pragma unroll
            for (int i = 0; i < 4; i++)
                #pragma unroll
                for (int j = 0; j < 4; j++)
                    acc[i][j] = fmaf(rp[i], rv[j], acc[i][j]);
        }

        const int b = bh >> 4, h = bh & 15;
        #pragma unroll
        for (int i = 0; i < 4; i++) {
            int gi = qstart + ty*4 + i;
            #pragma unroll
            for (int j = 0; j < 4; j++) {
                g_att[((long)(b*S_LEN + gi))*D_MODEL + h*DHEAD + tx*4 + j] = acc[i][j];
            }
        }
    }
}

// ---------------------------------------------------------------------------
extern "C" void kernel_launch(void* const* d_in, const int* in_sizes, int n_in,
                              void* d_out, int out_size)
{
    const float* x    = (const float*)d_in[0];
    const float* bias = (const float*)d_in[1];
    // d_in[2] = causal mask (recomputed analytically in-kernel)
    const float* Wqkv = (const float*)d_in[3];
    const float* Wout = (const float*)d_in[4];
    float* out = (float*)d_out;

    cudaFuncSetAttribute(attn_kernel,
                         cudaFuncAttributeMaxDynamicSharedMemorySize,
                         ATTN_SMEM_FLOATS * (int)sizeof(float));

    // A: QKV projection  (M=4096, N=3072), 3xTF32 tensor-core GEMM
    tf32_gemm_kernel<3072, true><<<dim3(24, 32), 256>>>(x, Wqkv, nullptr);

    // B: banded attention (32 q-tiles x 32 (b,h))
    attn_kernel<<<dim3(32, 32), 256, ATTN_SMEM_FLOATS * (int)sizeof(float)>>>(bias);

    // C: output projection (M=4096, N=1024), 3xTF32 tensor-core GEMM
    tf32_gemm_kernel<1024, false><<<dim3(8, 32), 256>>>(nullptr, Wout, out);
}